// round 3
// baseline (speedup 1.0000x reference)
#include <cuda_runtime.h>
#include <cstdint>

// MoEVM_62380105007239 — soft-ALU over one-hot byte encodings.
// R3: split into a pure-read decode kernel and a pure-write expand kernel.
// The whole 256 MB output is a function of 8 bytes per batch element
// (u32 sum, u32 xor), so a 512 KB L2-resident scratch decouples the two
// DRAM streams and avoids read/write bus turnaround.

static __device__ uint2 g_scratch[65536];

static __device__ __forceinline__ float onehot_val(int j, int s, float tiny) {
    if (j == s) return 1.0f;
    if (((j ^ s) & 0xF0) == 0 || ((j ^ s) & 0x0F) == 0) return tiny;
    return 0.0f;
}

// ── Kernel A: pure-read decode. One warp per batch element (8 KB read). ──
__global__ void __launch_bounds__(256, 6) decode_kernel(
    const float4* __restrict__ a4,
    const float4* __restrict__ b4,
    int B)
{
    const int warp = blockIdx.x * (blockDim.x >> 5) + (threadIdx.x >> 5);
    const int lane = threadIdx.x & 31;
    if (warp >= B) return;

    const float4* __restrict__ pa = a4 + (size_t)warp * 256;
    const float4* __restrict__ pb = b4 + (size_t)warp * 256;

    // FMA decode: one-hot dot index == the index. Slot s = r>>1 is
    // compile-time uniform per unrolled iteration.
    float accA[4] = {0.f, 0.f, 0.f, 0.f};
    float accB[4] = {0.f, 0.f, 0.f, 0.f};
    #pragma unroll
    for (int r = 0; r < 8; r++) {
        const int   f4 = lane + 32 * r;
        const float j  = (float)(lane * 4 + 128 * (r & 1)); // byte idx of .x
        const float4 xa = __ldcs(pa + f4);
        const float4 xb = __ldcs(pb + f4);
        const int s = r >> 1;
        accA[s] += xa.x * j + xa.y * (j + 1.f) + xa.z * (j + 2.f) + xa.w * (j + 3.f);
        accB[s] += xb.x * j + xb.y * (j + 1.f) + xb.z * (j + 2.f) + xb.w * (j + 3.f);
    }

    unsigned ia = (unsigned)(int)accA[0]
                | ((unsigned)(int)accA[1] << 8)
                | ((unsigned)(int)accA[2] << 16)
                | ((unsigned)(int)accA[3] << 24);
    unsigned ib = (unsigned)(int)accB[0]
                | ((unsigned)(int)accB[1] << 8)
                | ((unsigned)(int)accB[2] << 16)
                | ((unsigned)(int)accB[3] << 24);
    const unsigned va = __reduce_or_sync(0xFFFFFFFFu, ia);
    const unsigned vb = __reduce_or_sync(0xFFFFFFFFu, ib);

    if (lane == 0)
        g_scratch[warp] = make_uint2(va + vb, va ^ vb);  // (sum, xor)
}

// ── Kernel B: pure-write expand. 64 threads per output element (4 KB). ──
// Thread t (t = 0..63 within its group) writes float4 indices t, t+64,
// t+128, t+192 of its element: slot = k, j = t*4 — fully coalesced 1 KB
// per 64-lane group per unrolled store.
__global__ void __launch_bounds__(256, 8) write_kernel(
    float4* __restrict__ o4,
    int B)
{
    const int g   = threadIdx.x >> 6;               // 0..3: element-in-block
    const int t   = threadIdx.x & 63;
    const int blk = blockIdx.x * 4 + g;             // 0..2B-1
    if (blk >= 2 * B) return;

    const bool  isxor = (blk >= B);
    const int   elem  = isxor ? blk - B : blk;
    const uint2 s     = g_scratch[elem];            // L2-resident broadcast
    const unsigned v  = isxor ? s.y : s.x;

    const float TINY = 3.7200760e-44f;              // expf(-100), subnormal
    float4* __restrict__ dst = o4 + (size_t)blk * 256;
    const int j = t * 4;

    #pragma unroll
    for (int k = 0; k < 4; k++) {
        const int sb = (int)((v >> (8 * k)) & 255u);
        float4 o;
        o.x = onehot_val(j    , sb, TINY);
        o.y = onehot_val(j + 1, sb, TINY);
        o.z = onehot_val(j + 2, sb, TINY);
        o.w = onehot_val(j + 3, sb, TINY);
        __stcs(dst + t + 64 * k, o);
    }
}

extern "C" void kernel_launch(void* const* d_in, const int* in_sizes, int n_in,
                              void* d_out, int out_size)
{
    const float4* a = (const float4*)d_in[0];
    const float4* b = (const float4*)d_in[1];
    float4* out = (float4*)d_out;

    const int B = in_sizes[0] / 1024;               // inputs are [B,4,256]

    const int gridA = (B * 32 + 255) / 256;         // warp per element
    decode_kernel<<<gridA, 256>>>(a, b, B);

    const int gridB = (2 * B + 3) / 4;              // 4 elements per block
    write_kernel<<<gridB, 256>>>(out, B);
}

// round 4
// speedup vs baseline: 1.1007x; 1.1007x over previous
#include <cuda_runtime.h>
#include <cstdint>

// MoEVM_62380105007239 — soft-ALU over one-hot byte encodings.
// R4: fused single kernel (R3 split proved both directions cap at the same
// ~79% DRAM ceiling), restructured for stream locality: each warp owns
// exactly ONE 4KB read stream and ONE 4KB write stream.
//   warps 0-3 of a block: read a[e], decode, later write add-output[e]
//   warps 4-7:            read b[e], decode, later write xor-output[e]
// The 4 decoded bytes per element are exchanged through 32 B of SMEM.
// Output values: 1.0 at result byte, exp(-100) (fp32 subnormal) at bytes
// sharing a nibble, 0 elsewhere — exactly what SCALE=100 softmax yields.

static __device__ __forceinline__ float onehot_val(int j, int s, float tiny) {
    if (j == s) return 1.0f;
    if (((j ^ s) & 0xF0) == 0 || ((j ^ s) & 0x0F) == 0) return tiny;
    return 0.0f;
}

__global__ void __launch_bounds__(256, 6) moe_alu_kernel(
    const float4* __restrict__ a4,
    const float4* __restrict__ b4,
    float4* __restrict__ o4,
    int B)
{
    __shared__ unsigned sm[2][4];

    const int wid  = threadIdx.x >> 5;      // 0..7
    const int lane = threadIdx.x & 31;
    const int g    = wid & 3;                // element slot within block
    const int role = wid >> 2;               // 0: a / add-half, 1: b / xor-half
    const int e    = blockIdx.x * 4 + g;     // batch element
    const bool live = (e < B);

    // ── Read phase: one 4 KB sequential stream per warp ──
    unsigned v = 0;
    if (live) {
        const float4* __restrict__ src =
            (role == 0 ? a4 : b4) + (size_t)e * 256;

        // FMA decode: one-hot dot index == the index (index 0 contributes 0,
        // correct for the OR-pack). Slot s = r>>1 is uniform per iteration.
        float acc[4] = {0.f, 0.f, 0.f, 0.f};
        #pragma unroll
        for (int r = 0; r < 8; r++) {
            const float4 x = __ldcs(src + lane + 32 * r);
            const float  j = (float)(lane * 4 + 128 * (r & 1));
            acc[r >> 1] += x.x * j + x.y * (j + 1.f)
                         + x.z * (j + 2.f) + x.w * (j + 3.f);
        }
        unsigned iv = (unsigned)(int)acc[0]
                    | ((unsigned)(int)acc[1] << 8)
                    | ((unsigned)(int)acc[2] << 16)
                    | ((unsigned)(int)acc[3] << 24);
        v = __reduce_or_sync(0xFFFFFFFFu, iv);
        if (lane == 0) sm[role][g] = v;
    }
    __syncthreads();

    if (!live) return;

    const unsigned va = sm[0][g];
    const unsigned vb = sm[1][g];
    const unsigned res = (role == 0) ? (va + vb)   // LE carry chain == u32 add
                                     : (va ^ vb);  // bytewise xor

    const float TINY = 3.7200760e-44f;             // expf(-100), subnormal

    // ── Write phase: one 4 KB sequential stream per warp ──
    float4* __restrict__ dst = o4 + ((size_t)role * B + e) * 256;
    #pragma unroll
    for (int r = 0; r < 8; r++) {
        const int j  = lane * 4 + 128 * (r & 1);   // byte idx of component .x
        const int sb = (int)((res >> ((r >> 1) * 8)) & 255u);
        float4 o;
        o.x = onehot_val(j    , sb, TINY);
        o.y = onehot_val(j + 1, sb, TINY);
        o.z = onehot_val(j + 2, sb, TINY);
        o.w = onehot_val(j + 3, sb, TINY);
        __stcs(dst + lane + 32 * r, o);
    }
}

extern "C" void kernel_launch(void* const* d_in, const int* in_sizes, int n_in,
                              void* d_out, int out_size)
{
    const float4* a = (const float4*)d_in[0];
    const float4* b = (const float4*)d_in[1];
    float4* out = (float4*)d_out;

    const int B = in_sizes[0] / 1024;      // inputs are [B,4,256] floats
    const int blocks = (B + 3) / 4;        // 4 elements per 8-warp block
    moe_alu_kernel<<<blocks, 256>>>(a, b, out, B);
}